// round 1
// baseline (speedup 1.0000x reference)
#include <cuda_runtime.h>

#define N_  2048
#define E_  8192
#define ND_ 32
#define ED_ 16
#define H_  128
#define G_  128
#define TE_ 64
#define BN_EPS 1e-5f

// ---------------- device scratch (no allocations allowed) ----------------
__device__ float g_h[N_ * H_];
__device__ float g_xnew[N_ * H_];
__device__ float g_agg[N_ * H_];
__device__ float g_deg[N_];
__device__ float g_stats[2 * H_];   // [0:H) colsum, [H:2H) colsumsq
__device__ float g_pool[G_ * H_];
__device__ float g_gcnt[G_];

// ---------------- zero kernels ----------------
__global__ void zero_init_kernel() {
    int i = blockIdx.x * 256 + threadIdx.x;
    if (i < N_)       g_deg[i] = 0.f;
    if (i < G_)       g_gcnt[i] = 0.f;
    if (i < G_ * H_)  g_pool[i] = 0.f;
}

__global__ void zero_layer_kernel() {
    int i = blockIdx.x * 256 + threadIdx.x;
    if (i < N_ * H_)  g_agg[i] = 0.f;
    if (i < 2 * H_)   g_stats[i] = 0.f;
}

// ---------------- degree / graph-size counts ----------------
__global__ void counts_kernel(const int* __restrict__ edge_index,
                              const int* __restrict__ batch) {
    int i = blockIdx.x * 256 + threadIdx.x;
    if (i < E_) atomicAdd(&g_deg[edge_index[E_ + i]], 1.f);
    if (i < N_) atomicAdd(&g_gcnt[batch[i]], 1.f);
}

// ---------------- node encoder: h = x @ node_W + node_b ----------------
__global__ void __launch_bounds__(128)
enc_kernel(const float* __restrict__ x, const float* __restrict__ nW,
           const float* __restrict__ nb) {
    __shared__ float xs[16][ND_ + 1];
    int o = threadIdx.x;
    int r0 = blockIdx.x * 16;
    for (int idx = o; idx < 16 * ND_; idx += 128) {
        int r = idx >> 5, k = idx & 31;
        xs[r][k] = x[(r0 + r) * ND_ + k];
    }
    __syncthreads();
    float acc[16];
#pragma unroll
    for (int r = 0; r < 16; ++r) acc[r] = 0.f;
    for (int k = 0; k < ND_; ++k) {
        float w = nW[k * H_ + o];
#pragma unroll
        for (int r = 0; r < 16; ++r) acc[r] += xs[r][k] * w;
    }
    float b = nb[o];
#pragma unroll
    for (int r = 0; r < 16; ++r) g_h[(r0 + r) * H_ + o] = acc[r] + b;
}

// ---------------- the big one: fused edge-conditioned message GEMM ----------------
// msg[e,o] = sum_{d,i} ea[e,d]*h[src[e],i]*eW[d,i*H+o] + sum_i h[src[e],i]*eb[i*H+o]
// scattered via atomicAdd into g_agg[dst[e]] (sum; divided by deg later).
// Block: TE_=64 edges x all 128 outputs, 256 threads (16x16), thread tile 4e x 8o
// (8 outputs held as 4 packed f32x2 accumulators -> fma.rn.f32x2, 2x fp32 rate).
__global__ void __launch_bounds__(256, 1)
msg_kernel(const int* __restrict__ edge_index,
           const float* __restrict__ edge_attr,
           const float* __restrict__ eW,     // edge_W + l*ED*H*H
           const float* __restrict__ ebias)  // edge_b + l*H*H
{
    extern __shared__ float sm[];
    float* ea_s = sm;                          // [TE][ED]        1024 f
    float* h_s  = sm + TE_ * ED_;              // [TE][H+1]       8256 f
    float* A_s  = h_s + TE_ * (H_ + 1);        // [TE][H+1]       8256 f
    float* B_s  = A_s + TE_ * (H_ + 1);        // [64][H]         8192 f
    __shared__ int src_s[TE_], dst_s[TE_];

    const int tid = threadIdx.x;
    const int tx = tid & 15;      // output group: o0 = tx*8
    const int ty = tid >> 4;      // edge group:   e0 = ty*4
    const int e0 = blockIdx.x * TE_;

    if (tid < TE_) {
        src_s[tid] = edge_index[e0 + tid];
        dst_s[tid] = edge_index[E_ + e0 + tid];
    }
    for (int idx = tid; idx < TE_ * ED_; idx += 256)
        ea_s[idx] = edge_attr[e0 * ED_ + idx];          // contiguous chunk
    __syncthreads();
    for (int idx = tid; idx < TE_ * H_; idx += 256) {
        int e = idx >> 7, i = idx & 127;
        h_s[e * (H_ + 1) + i] = g_h[src_s[e] * H_ + i]; // gather
    }

    unsigned long long acc[4][4];
#pragma unroll
    for (int j = 0; j < 4; ++j)
#pragma unroll
        for (int p = 0; p < 4; ++p) acc[j][p] = 0ull;

    for (int d = 0; d <= ED_; ++d) {            // d == ED_ -> bias "row"
        const float* Bg = (d < ED_) ? (eW + d * H_ * H_) : ebias;
        __syncthreads();                        // A_s readers of prev d done
        const float* Aptr;
        if (d < ED_) {
            for (int idx = tid; idx < TE_ * H_; idx += 256) {
                int e = idx >> 7, i = idx & 127;
                A_s[e * (H_ + 1) + i] = ea_s[e * ED_ + d] * h_s[e * (H_ + 1) + i];
            }
            Aptr = A_s;
        } else {
            Aptr = h_s;                          // a = 1 * h for the bias part
        }
        for (int ic = 0; ic < H_; ic += 64) {
            __syncthreads();                     // A built; prior B_s readers done
            for (int idx = tid; idx < 64 * H_; idx += 256)
                B_s[idx] = Bg[ic * H_ + idx];    // contiguous 32KB stage
            __syncthreads();
            const float* Arow = Aptr + (ty * 4) * (H_ + 1) + ic;
#pragma unroll 4
            for (int i2 = 0; i2 < 64; ++i2) {
                const ulonglong2* bp =
                    reinterpret_cast<const ulonglong2*>(B_s + i2 * H_ + tx * 8);
                ulonglong2 u = bp[0];
                ulonglong2 v = bp[1];
#pragma unroll
                for (int j = 0; j < 4; ++j) {
                    float a = Arow[j * (H_ + 1) + i2];
                    unsigned long long ap;
                    asm("mov.b64 %0, {%1, %1};" : "=l"(ap) : "f"(a));
                    asm("fma.rn.f32x2 %0, %1, %2, %0;" : "+l"(acc[j][0]) : "l"(ap), "l"(u.x));
                    asm("fma.rn.f32x2 %0, %1, %2, %0;" : "+l"(acc[j][1]) : "l"(ap), "l"(u.y));
                    asm("fma.rn.f32x2 %0, %1, %2, %0;" : "+l"(acc[j][2]) : "l"(ap), "l"(v.x));
                    asm("fma.rn.f32x2 %0, %1, %2, %0;" : "+l"(acc[j][3]) : "l"(ap), "l"(v.y));
                }
            }
        }
    }

    // epilogue: scatter-add into agg[dst]
#pragma unroll
    for (int j = 0; j < 4; ++j) {
        float* dstp = g_agg + dst_s[ty * 4 + j] * H_ + tx * 8;
#pragma unroll
        for (int p = 0; p < 4; ++p) {
            float lo, hi;
            asm("mov.b64 {%0, %1}, %2;" : "=f"(lo), "=f"(hi) : "l"(acc[j][p]));
            atomicAdd(dstp + p * 2,     lo);
            atomicAdd(dstp + p * 2 + 1, hi);
        }
    }
}

// ---------------- x_new = h @ root_W + agg/deg + bias ; accumulate BN stats ----------------
__global__ void __launch_bounds__(128)
xnew_kernel(const float* __restrict__ rootW, const float* __restrict__ cbias) {
    __shared__ float hs[16][H_ + 1];
    int o = threadIdx.x;
    int r0 = blockIdx.x * 16;
    for (int idx = o; idx < 16 * H_; idx += 128) {
        int r = idx >> 7, i = idx & 127;
        hs[r][i] = g_h[(r0 + r) * H_ + i];
    }
    __syncthreads();
    float acc[16];
#pragma unroll
    for (int r = 0; r < 16; ++r) acc[r] = 0.f;
    for (int k = 0; k < H_; ++k) {
        float w = rootW[k * H_ + o];
#pragma unroll
        for (int r = 0; r < 16; ++r) acc[r] += hs[r][k] * w;
    }
    float cb = cbias[o];
    float s = 0.f, sq = 0.f;
#pragma unroll
    for (int r = 0; r < 16; ++r) {
        int n = r0 + r;
        float v = acc[r] + g_agg[n * H_ + o] / fmaxf(g_deg[n], 1.f) + cb;
        g_xnew[n * H_ + o] = v;
        s += v;
        sq += v * v;
    }
    atomicAdd(&g_stats[o], s);
    atomicAdd(&g_stats[H_ + o], sq);
}

// ---------------- BN(train-stats) + ReLU + residual ----------------
__global__ void bn_kernel(const float* __restrict__ gamma,
                          const float* __restrict__ beta) {
    int idx = blockIdx.x * 256 + threadIdx.x;   // N*H threads
    int o = idx & (H_ - 1);
    float mu  = g_stats[o] * (1.f / N_);
    float var = g_stats[H_ + o] * (1.f / N_) - mu * mu;
    float v = (g_xnew[idx] - mu) * rsqrtf(var + BN_EPS) * gamma[o] + beta[o];
    g_h[idx] += fmaxf(v, 0.f);
}

// ---------------- global mean pool (sum; divide in classifier) ----------------
__global__ void pool_kernel(const int* __restrict__ batch) {
    int idx = blockIdx.x * 256 + threadIdx.x;   // N*H threads
    int n = idx >> 7, o = idx & 127;
    atomicAdd(&g_pool[batch[n] * H_ + o], g_h[idx]);
}

// ---------------- classifier ----------------
__global__ void __launch_bounds__(64)
cls_kernel(const float* __restrict__ W1, const float* __restrict__ b1,
           const float* __restrict__ W2, const float* __restrict__ b2,
           float* __restrict__ out) {
    __shared__ float gv[H_];
    __shared__ float part[2];
    int g = blockIdx.x, j = threadIdx.x;        // 64 threads
    float inv = 1.f / fmaxf(g_gcnt[g], 1.f);
    gv[j]      = g_pool[g * H_ + j] * inv;
    gv[j + 64] = g_pool[g * H_ + 64 + j] * inv;
    __syncthreads();
    float a = b1[j];
    for (int k = 0; k < H_; ++k) a += gv[k] * W1[k * 64 + j];
    float v = fmaxf(a, 0.f) * W2[j];
#pragma unroll
    for (int off = 16; off > 0; off >>= 1)
        v += __shfl_down_sync(0xffffffffu, v, off);
    if ((j & 31) == 0) part[j >> 5] = v;
    __syncthreads();
    if (j == 0) out[g] = part[0] + part[1] + b2[0];
}

// ---------------- launch ----------------
extern "C" void kernel_launch(void* const* d_in, const int* in_sizes, int n_in,
                              void* d_out, int out_size) {
    const float* x          = (const float*)d_in[0];
    const int*   edge_index = (const int*)  d_in[1];
    const float* edge_attr  = (const float*)d_in[2];
    const int*   batch      = (const int*)  d_in[3];
    const float* node_W     = (const float*)d_in[4];
    const float* node_b     = (const float*)d_in[5];
    const float* edge_W     = (const float*)d_in[6];
    const float* edge_b     = (const float*)d_in[7];
    const float* root_W     = (const float*)d_in[8];
    const float* conv_bias  = (const float*)d_in[9];
    const float* bn_gamma   = (const float*)d_in[10];
    const float* bn_beta    = (const float*)d_in[11];
    const float* cls_W1     = (const float*)d_in[12];
    const float* cls_b1     = (const float*)d_in[13];
    const float* cls_W2     = (const float*)d_in[14];
    const float* cls_b2     = (const float*)d_in[15];
    float* out = (float*)d_out;

    const int msg_smem = (TE_ * ED_ + 2 * TE_ * (H_ + 1) + 64 * H_) * 4;  // ~100.5 KB
    cudaFuncSetAttribute((const void*)msg_kernel,
                         cudaFuncAttributeMaxDynamicSharedMemorySize, msg_smem);

    zero_init_kernel<<<(G_ * H_ + 255) / 256, 256>>>();
    counts_kernel<<<(E_ + 255) / 256, 256>>>(edge_index, batch);
    enc_kernel<<<N_ / 16, 128>>>(x, node_W, node_b);

    for (int l = 0; l < 3; ++l) {
        zero_layer_kernel<<<(N_ * H_) / 256, 256>>>();
        msg_kernel<<<E_ / TE_, 256, msg_smem>>>(
            edge_index, edge_attr,
            edge_W + (size_t)l * ED_ * H_ * H_,
            edge_b + (size_t)l * H_ * H_);
        xnew_kernel<<<N_ / 16, 128>>>(root_W + l * H_ * H_, conv_bias + l * H_);
        bn_kernel<<<(N_ * H_) / 256, 256>>>(bn_gamma + l * H_, bn_beta + l * H_);
    }

    pool_kernel<<<(N_ * H_) / 256, 256>>>(batch);
    cls_kernel<<<G_, 64>>>(cls_W1, cls_b1, cls_W2, cls_b2, out);
}

// round 2
// speedup vs baseline: 3.1783x; 3.1783x over previous
#include <cuda_runtime.h>
#include <cstdint>

#define N_  2048
#define E_  8192
#define ND_ 32
#define ED_ 16
#define H_  128
#define G_  128
#define L_  3
#define TE_ 64          // edges per block in msg kernel
#define BN_EPS 1e-5f

// ---------------- device scratch (no allocations allowed) ----------------
__device__ float g_h[N_ * H_];
__device__ float g_xnew[N_ * H_];
__device__ float g_agg3[L_ * N_ * H_];
__device__ float g_deg[N_];
__device__ float g_stats[L_ * 2 * H_];
__device__ float g_pool[G_ * H_];
__device__ float g_gcnt[G_];
// tf32-rounded, transposed edge weights: [L][17][n=128][k=128]; chunk 16 = bias
__device__ float g_eWt[L_ * 17 * H_ * H_];

// ---------------- helpers ----------------
__device__ __forceinline__ float tf32r(float x) {
    uint32_t u;
    asm("cvt.rna.tf32.f32 %0, %1;" : "=r"(u) : "f"(x));
    return __uint_as_float(u);
}

#define LDSM4(r0, r1, r2, r3, addr)                                          \
    asm volatile("ldmatrix.sync.aligned.m8n8.x4.shared.b16 {%0,%1,%2,%3}, [%4];" \
                 : "=r"(r0), "=r"(r1), "=r"(r2), "=r"(r3) : "r"(addr))

#define MMA_TF32(c, a, b0, b1)                                               \
    asm volatile("mma.sync.aligned.m16n8k8.row.col.f32.tf32.tf32.f32 "       \
                 "{%0,%1,%2,%3}, {%4,%5,%6,%7}, {%8,%9}, {%0,%1,%2,%3};"     \
                 : "+f"((c)[0]), "+f"((c)[1]), "+f"((c)[2]), "+f"((c)[3])    \
                 : "r"((a)[0]), "r"((a)[1]), "r"((a)[2]), "r"((a)[3]),       \
                   "r"(b0), "r"(b1))

// ---------------- one-time zero ----------------
__global__ void zero_init_kernel() {
    int i = blockIdx.x * 256 + threadIdx.x;             // L*N*H grid
    if (i < L_ * N_ * H_)  g_agg3[i] = 0.f;
    if (i < N_)            g_deg[i] = 0.f;
    if (i < G_)            g_gcnt[i] = 0.f;
    if (i < G_ * H_)       g_pool[i] = 0.f;
    if (i < L_ * 2 * H_)   g_stats[i] = 0.f;
}

// ---------------- prep: round to tf32 + transpose edge_W/edge_b ----------------
// out[l][d][n*128+k] = tf32( d<16 ? edge_W[l][d][k*128+n] : edge_b[l][k*128+n] )
__global__ void prep_kernel(const float* __restrict__ edge_W,
                            const float* __restrict__ edge_b) {
    int idx = blockIdx.x * 256 + threadIdx.x;           // L*17*16384
    if (idx >= L_ * 17 * H_ * H_) return;
    int ld = idx >> 14, j = idx & 16383;
    int l = ld / 17, d = ld - l * 17;
    int n = j >> 7, k = j & 127;
    float v = (d < 16) ? edge_W[((l * 16 + d) << 14) + k * H_ + n]
                       : edge_b[(l << 14) + k * H_ + n];
    g_eWt[idx] = tf32r(v);
}

// ---------------- degree / graph-size counts ----------------
__global__ void counts_kernel(const int* __restrict__ edge_index,
                              const int* __restrict__ batch) {
    int i = blockIdx.x * 256 + threadIdx.x;
    if (i < E_) atomicAdd(&g_deg[edge_index[E_ + i]], 1.f);
    if (i < N_) atomicAdd(&g_gcnt[batch[i]], 1.f);
}

// ---------------- node encoder: h = x @ node_W + node_b ----------------
__global__ void __launch_bounds__(128)
enc_kernel(const float* __restrict__ x, const float* __restrict__ nW,
           const float* __restrict__ nb) {
    __shared__ float xs[16][ND_ + 1];
    int o = threadIdx.x;
    int r0 = blockIdx.x * 16;
    for (int idx = o; idx < 16 * ND_; idx += 128) {
        int r = idx >> 5, k = idx & 31;
        xs[r][k] = x[(r0 + r) * ND_ + k];
    }
    __syncthreads();
    float acc[16];
#pragma unroll
    for (int r = 0; r < 16; ++r) acc[r] = 0.f;
    for (int k = 0; k < ND_; ++k) {
        float w = nW[k * H_ + o];
#pragma unroll
        for (int r = 0; r < 16; ++r) acc[r] += xs[r][k] * w;
    }
    float b = nb[o];
#pragma unroll
    for (int r = 0; r < 16; ++r) g_h[(r0 + r) * H_ + o] = acc[r] + b;
}

// ---------------- msg: tf32 tensor-core edge-conditioned GEMM ----------------
// Per block: 64 edges, N=128 outputs, K = 17*128 (16 edge_attr dims + bias).
// A[e, d*128+i] = tf32(ea[e,d] * h[src[e], i]) built per-d in smem.
// B chunk d = g_eWt[l][d] ([n][k] layout), cp.async double-buffered.
// Warp tile 32x32 (8 warps, 2x4). Results scatter-atomicAdd into agg[dst].
//
// smem (floats): ea[64*16]=1024 | h[64*132]=8448 | A[64*132]=8448 | B[2][128*132]
#define SA 132
#define A_OFF   (1024 + 64 * SA)
#define B_OFF   (A_OFF + 64 * SA)
#define BBUF    (128 * SA)
#define SMEM_F  (B_OFF + 2 * BBUF)

__global__ void __launch_bounds__(256, 1)
msg_kernel(const int* __restrict__ edge_index,
           const float* __restrict__ edge_attr,
           const float* __restrict__ eWt,     // g_eWt + l*17*16384
           float* __restrict__ aggp)          // g_agg3 + l*N*H
{
    extern __shared__ float sm[];
    float* ea_s = sm;
    float* h_s  = sm + 1024;
    float* A_s  = sm + A_OFF;
    float* B_s  = sm + B_OFF;
    __shared__ int src_s[TE_], dst_s[TE_];

    const int tid  = threadIdx.x;
    const int lane = tid & 31;
    const int wid  = tid >> 5;
    const int wm   = wid & 1;        // M half  (rows wm*32)
    const int wn   = wid >> 1;       // N quarter (cols wn*32)
    const int e0   = blockIdx.x * TE_;

    const uint32_t smb = (uint32_t)__cvta_generic_to_shared(sm);

    // ---- prologue fills ----
    if (tid < TE_) {
        src_s[tid] = edge_index[e0 + tid];
        dst_s[tid] = edge_index[E_ + e0 + tid];
    }
    for (int idx = tid; idx < TE_ * ED_; idx += 256)
        ea_s[idx] = edge_attr[e0 * ED_ + idx];
    __syncthreads();                  // src_s ready
    for (int idx = tid; idx < TE_ * H_; idx += 256) {
        int e = idx >> 7, i = idx & 127;
        h_s[e * SA + i] = g_h[src_s[e] * H_ + i];
    }

    // ---- stage B chunk 0 ----
    {
        const float* gsrc = eWt;      // d = 0
#pragma unroll
        for (int j = 0; j < 16; ++j) {
            int c = tid + j * 256;            // 4096 float4 chunks
            int n = c >> 5, f4 = (c & 31) << 2;
            uint32_t dst = smb + (B_OFF + n * SA + f4) * 4;
            asm volatile("cp.async.cg.shared.global [%0], [%1], 16;"
                         :: "r"(dst), "l"(gsrc + n * H_ + f4));
        }
        asm volatile("cp.async.commit_group;");
    }
    __syncthreads();                  // h_s / ea_s ready for builds

    // ---- per-lane ldmatrix addresses (k-offset added per kstep) ----
    const int mrow = (lane & 7) + ((lane >> 3) & 1) * 8;   // row-in-16 pattern
    const int coff = (lane >> 4) * 4;                      // col 0 or 4
    uint32_t aaddr0 = smb + ((A_OFF + (wm * 32 + mrow)      * SA + coff) << 2);
    uint32_t aaddr1 = smb + ((A_OFF + (wm * 32 + 16 + mrow) * SA + coff) << 2);
    uint32_t baddr0 = smb + ((B_OFF + (wn * 32 + mrow)      * SA + coff) << 2);
    uint32_t baddr1 = smb + ((B_OFF + (wn * 32 + 16 + mrow) * SA + coff) << 2);

    float acc[2][4][4];
#pragma unroll
    for (int mt = 0; mt < 2; ++mt)
#pragma unroll
        for (int nt = 0; nt < 4; ++nt)
#pragma unroll
            for (int p = 0; p < 4; ++p) acc[mt][nt][p] = 0.f;

    const int be = tid & 63, bq = tid >> 6;    // A-build mapping
    const float* hrow = h_s + be * SA + bq * 32;
    float*       arow = A_s + be * SA + bq * 32;

    for (int d = 0; d <= 16; ++d) {
        const int cur = d & 1;
        // stage next chunk into other buffer
        if (d < 16) {
            const float* gsrc = eWt + ((d + 1) << 14);
            uint32_t bbase = (uint32_t)(B_OFF + (cur ^ 1) * BBUF);
#pragma unroll
            for (int j = 0; j < 16; ++j) {
                int c = tid + j * 256;
                int n = c >> 5, f4 = (c & 31) << 2;
                uint32_t dst = smb + ((bbase + n * SA + f4) << 2);
                asm volatile("cp.async.cg.shared.global [%0], [%1], 16;"
                             :: "r"(dst), "l"(gsrc + n * H_ + f4));
            }
            asm volatile("cp.async.commit_group;");
        }
        // build A_s for chunk d (prev mma finished reading A_s: trailing sync)
        {
            float eav = (d < 16) ? ea_s[be * ED_ + d] : 1.f;
#pragma unroll
            for (int i = 0; i < 32; i += 4) {
                float4 v = *reinterpret_cast<const float4*>(hrow + i);
                float4 w;
                w.x = tf32r(eav * v.x); w.y = tf32r(eav * v.y);
                w.z = tf32r(eav * v.z); w.w = tf32r(eav * v.w);
                *reinterpret_cast<float4*>(arow + i) = w;
            }
        }
        if (d < 16) asm volatile("cp.async.wait_group 1;");
        else        asm volatile("cp.async.wait_group 0;");
        __syncthreads();              // A_s + B_s[cur] published

        // ---- 16 k-steps of mma over this 128-wide chunk ----
        const uint32_t bsel = (uint32_t)(cur * BBUF) << 2;
        uint32_t ba0 = baddr0 + bsel, ba1 = baddr1 + bsel;
#pragma unroll 4
        for (int ks = 0; ks < 16; ++ks) {
            const uint32_t ko = ks * 32;    // 8 floats = 32B
            uint32_t A0[4], A1[4], B0[4], B1[4];
            LDSM4(A0[0], A0[1], A0[2], A0[3], aaddr0 + ko);
            LDSM4(A1[0], A1[1], A1[2], A1[3], aaddr1 + ko);
            LDSM4(B0[0], B0[1], B0[2], B0[3], ba0 + ko);
            LDSM4(B1[0], B1[1], B1[2], B1[3], ba1 + ko);
            MMA_TF32(acc[0][0], A0, B0[0], B0[2]);
            MMA_TF32(acc[0][1], A0, B0[1], B0[3]);
            MMA_TF32(acc[0][2], A0, B1[0], B1[2]);
            MMA_TF32(acc[0][3], A0, B1[1], B1[3]);
            MMA_TF32(acc[1][0], A1, B0[0], B0[2]);
            MMA_TF32(acc[1][1], A1, B0[1], B0[3]);
            MMA_TF32(acc[1][2], A1, B1[0], B1[2]);
            MMA_TF32(acc[1][3], A1, B1[1], B1[3]);
        }
        __syncthreads();              // done reading A_s / B_s[cur]
    }

    // ---- epilogue: scatter-add into agg[dst] ----
#pragma unroll
    for (int mt = 0; mt < 2; ++mt) {
        int e_lo = wm * 32 + mt * 16 + (lane >> 2);
        int d_lo = dst_s[e_lo] * H_;
        int d_hi = dst_s[e_lo + 8] * H_;
#pragma unroll
        for (int nt = 0; nt < 4; ++nt) {
            int col = wn * 32 + nt * 8 + (lane & 3) * 2;
            atomicAdd(aggp + d_lo + col,     acc[mt][nt][0]);
            atomicAdd(aggp + d_lo + col + 1, acc[mt][nt][1]);
            atomicAdd(aggp + d_hi + col,     acc[mt][nt][2]);
            atomicAdd(aggp + d_hi + col + 1, acc[mt][nt][3]);
        }
    }
}

// ---------------- x_new = h @ root_W + agg/deg + bias ; BN stats ----------------
__global__ void __launch_bounds__(128)
xnew_kernel(const float* __restrict__ rootW, const float* __restrict__ cbias,
            const float* __restrict__ aggp, float* __restrict__ statp) {
    __shared__ float hs[16][H_ + 1];
    int o = threadIdx.x;
    int r0 = blockIdx.x * 16;
    for (int idx = o; idx < 16 * H_; idx += 128) {
        int r = idx >> 7, i = idx & 127;
        hs[r][i] = g_h[(r0 + r) * H_ + i];
    }
    __syncthreads();
    float acc[16];
#pragma unroll
    for (int r = 0; r < 16; ++r) acc[r] = 0.f;
    for (int k = 0; k < H_; ++k) {
        float w = rootW[k * H_ + o];
#pragma unroll
        for (int r = 0; r < 16; ++r) acc[r] += hs[r][k] * w;
    }
    float cb = cbias[o];
    float s = 0.f, sq = 0.f;
#pragma unroll
    for (int r = 0; r < 16; ++r) {
        int n = r0 + r;
        float v = acc[r] + aggp[n * H_ + o] / fmaxf(g_deg[n], 1.f) + cb;
        g_xnew[n * H_ + o] = v;
        s += v;
        sq += v * v;
    }
    atomicAdd(&statp[o], s);
    atomicAdd(&statp[H_ + o], sq);
}

// ---------------- BN + ReLU + residual (+ pool on last layer) ----------------
__global__ void bn_kernel(const float* __restrict__ gamma,
                          const float* __restrict__ beta,
                          const float* __restrict__ statp,
                          const int* __restrict__ batch, int last) {
    int idx = blockIdx.x * 256 + threadIdx.x;   // N*H threads
    int o = idx & (H_ - 1);
    float mu  = statp[o] * (1.f / N_);
    float var = statp[H_ + o] * (1.f / N_) - mu * mu;
    float v = (g_xnew[idx] - mu) * rsqrtf(var + BN_EPS) * gamma[o] + beta[o];
    float hv = g_h[idx] + fmaxf(v, 0.f);
    g_h[idx] = hv;
    if (last) {
        int n = idx >> 7;
        atomicAdd(&g_pool[batch[n] * H_ + o], hv);
    }
}

// ---------------- classifier ----------------
__global__ void __launch_bounds__(64)
cls_kernel(const float* __restrict__ W1, const float* __restrict__ b1,
           const float* __restrict__ W2, const float* __restrict__ b2,
           float* __restrict__ out) {
    __shared__ float gv[H_];
    __shared__ float part[2];
    int g = blockIdx.x, j = threadIdx.x;        // 64 threads
    float inv = 1.f / fmaxf(g_gcnt[g], 1.f);
    gv[j]      = g_pool[g * H_ + j] * inv;
    gv[j + 64] = g_pool[g * H_ + 64 + j] * inv;
    __syncthreads();
    float a = b1[j];
    for (int k = 0; k < H_; ++k) a += gv[k] * W1[k * 64 + j];
    float v = fmaxf(a, 0.f) * W2[j];
#pragma unroll
    for (int off = 16; off > 0; off >>= 1)
        v += __shfl_down_sync(0xffffffffu, v, off);
    if ((j & 31) == 0) part[j >> 5] = v;
    __syncthreads();
    if (j == 0) out[g] = part[0] + part[1] + b2[0];
}

// ---------------- launch ----------------
extern "C" void kernel_launch(void* const* d_in, const int* in_sizes, int n_in,
                              void* d_out, int out_size) {
    const float* x          = (const float*)d_in[0];
    const int*   edge_index = (const int*)  d_in[1];
    const float* edge_attr  = (const float*)d_in[2];
    const int*   batch      = (const int*)  d_in[3];
    const float* node_W     = (const float*)d_in[4];
    const float* node_b     = (const float*)d_in[5];
    const float* edge_W     = (const float*)d_in[6];
    const float* edge_b     = (const float*)d_in[7];
    const float* root_W     = (const float*)d_in[8];
    const float* conv_bias  = (const float*)d_in[9];
    const float* bn_gamma   = (const float*)d_in[10];
    const float* bn_beta    = (const float*)d_in[11];
    const float* cls_W1     = (const float*)d_in[12];
    const float* cls_b1     = (const float*)d_in[13];
    const float* cls_W2     = (const float*)d_in[14];
    const float* cls_b2     = (const float*)d_in[15];
    float* out = (float*)d_out;

    float* d_agg3;  cudaGetSymbolAddress((void**)&d_agg3,  g_agg3);
    float* d_stats; cudaGetSymbolAddress((void**)&d_stats, g_stats);
    float* d_eWt;   cudaGetSymbolAddress((void**)&d_eWt,   g_eWt);

    const int msg_smem = SMEM_F * 4;   // ~202 KB
    static int attr_set = 0;
    cudaFuncSetAttribute((const void*)msg_kernel,
                         cudaFuncAttributeMaxDynamicSharedMemorySize, msg_smem);
    (void)attr_set;

    zero_init_kernel<<<(L_ * N_ * H_ + 255) / 256, 256>>>();
    prep_kernel<<<(L_ * 17 * H_ * H_ + 255) / 256, 256>>>(edge_W, edge_b);
    counts_kernel<<<(E_ + 255) / 256, 256>>>(edge_index, batch);
    enc_kernel<<<N_ / 16, 128>>>(x, node_W, node_b);

    for (int l = 0; l < L_; ++l) {
        msg_kernel<<<E_ / TE_, 256, msg_smem>>>(
            edge_index, edge_attr,
            d_eWt + (size_t)l * 17 * H_ * H_,
            d_agg3 + (size_t)l * N_ * H_);
        xnew_kernel<<<N_ / 16, 128>>>(root_W + l * H_ * H_, conv_bias + l * H_,
                                      d_agg3 + (size_t)l * N_ * H_,
                                      d_stats + l * 2 * H_);
        bn_kernel<<<(N_ * H_) / 256, 256>>>(bn_gamma + l * H_, bn_beta + l * H_,
                                            d_stats + l * 2 * H_, batch,
                                            l == L_ - 1);
    }

    cls_kernel<<<G_, 64>>>(cls_W1, cls_b1, cls_W2, cls_b2, out);
}

// round 3
// speedup vs baseline: 5.4526x; 1.7156x over previous
#include <cuda_runtime.h>
#include <cstdint>

#define N_  2048
#define E_  8192
#define ND_ 32
#define ED_ 16
#define H_  128
#define G_  128
#define L_  3
#define KD_ 17          // 16 edge dims + bias
#define ZW_ (KD_ * H_)  // 2176, z row width
#define BN_EPS 1e-5f

// ---------------- device scratch (no allocations allowed) ----------------
__device__ float g_h[N_ * H_];
__device__ float g_xnew[N_ * H_];
__device__ float g_agg3[L_ * N_ * H_];
__device__ float g_deg[N_];
__device__ float g_stats[L_ * 2 * H_];
__device__ float g_pool[G_ * H_];
__device__ float g_gcnt[G_];
__device__ float g_z[N_ * ZW_];                 // per-node transforms, 17.8 MB
// tf32-rounded, transposed edge weights: [L][17][n=o][k=i]; chunk 16 = bias
__device__ float g_eWt[L_ * KD_ * H_ * H_];

// ---------------- helpers ----------------
__device__ __forceinline__ float tf32r(float x) {
    uint32_t u;
    asm("cvt.rna.tf32.f32 %0, %1;" : "=r"(u) : "f"(x));
    return __uint_as_float(u);
}

#define LDSM4(r0, r1, r2, r3, addr)                                          \
    asm volatile("ldmatrix.sync.aligned.m8n8.x4.shared.b16 {%0,%1,%2,%3}, [%4];" \
                 : "=r"(r0), "=r"(r1), "=r"(r2), "=r"(r3) : "r"(addr))

#define MMA_TF32(c, a, b0, b1)                                               \
    asm volatile("mma.sync.aligned.m16n8k8.row.col.f32.tf32.tf32.f32 "       \
                 "{%0,%1,%2,%3}, {%4,%5,%6,%7}, {%8,%9}, {%0,%1,%2,%3};"     \
                 : "+f"((c)[0]), "+f"((c)[1]), "+f"((c)[2]), "+f"((c)[3])    \
                 : "r"((a)[0]), "r"((a)[1]), "r"((a)[2]), "r"((a)[3]),       \
                   "r"(b0), "r"(b1))

// ---------------- init: zero scratch + prep tf32-transposed weights ----------------
__global__ void init_kernel(const float* __restrict__ edge_W,
                            const float* __restrict__ edge_b) {
    int i = blockIdx.x * 256 + threadIdx.x;     // grid covers L*17*16384
    if (i < L_ * N_ * H_)  g_agg3[i] = 0.f;
    if (i < N_)            g_deg[i] = 0.f;
    if (i < G_)            g_gcnt[i] = 0.f;
    if (i < G_ * H_)       g_pool[i] = 0.f;
    if (i < L_ * 2 * H_)   g_stats[i] = 0.f;
    if (i < L_ * KD_ * H_ * H_) {
        int ld = i >> 14, j = i & 16383;
        int l = ld / KD_, d = ld - l * KD_;
        int n = j >> 7, k = j & 127;
        float v = (d < 16) ? edge_W[((l * 16 + d) << 14) + k * H_ + n]
                           : edge_b[(l << 14) + k * H_ + n];
        g_eWt[i] = tf32r(v);
    }
}

// ---------------- degree / graph-size counts ----------------
__global__ void counts_kernel(const int* __restrict__ edge_index,
                              const int* __restrict__ batch) {
    int i = blockIdx.x * 256 + threadIdx.x;
    if (i < E_) atomicAdd(&g_deg[edge_index[E_ + i]], 1.f);
    if (i < N_) atomicAdd(&g_gcnt[batch[i]], 1.f);
}

// ---------------- node encoder: elementwise thread per (n,o) ----------------
__global__ void __launch_bounds__(256)
enc_kernel(const float* __restrict__ x, const float* __restrict__ nW,
           const float* __restrict__ nb) {
    int idx = blockIdx.x * 256 + threadIdx.x;   // N*H
    int n = idx >> 7, o = idx & 127;
    const float* xr = x + n * ND_;
    float acc = nb[o];
#pragma unroll
    for (int k = 0; k < ND_; ++k) acc += xr[k] * nW[k * H_ + o];
    g_h[idx] = acc;
}

// ---------------- zgemm: z = tf32(h) @ eWt  (M=2048, N=2176, K=128) ----------------
// grid (8, 17): 256-row m tile x one 128-wide d chunk. 256 threads, 8 warps,
// warp tile 64x64. Single K pass (16 ksteps), no inner syncs.
#define ZSA 132
#define ZSMEM_F (256 * ZSA + 128 * ZSA)

__global__ void __launch_bounds__(256, 1)
zgemm_kernel(const float* __restrict__ eWt) {      // g_eWt + l*17*16384
    extern __shared__ float sm[];
    float* A_s = sm;                 // [256][132] tf32(h)
    float* B_s = sm + 256 * ZSA;     // [128][132] weights (n-major, k contig)

    const int tid  = threadIdx.x;
    const int lane = tid & 31;
    const int wid  = tid >> 5;
    const int wm   = wid >> 1;       // 0..3 -> m offset wm*64
    const int wn   = wid & 1;        // 0..1 -> n offset wn*64
    const int m0   = blockIdx.x * 256;
    const int d    = blockIdx.y;

    const uint32_t smb = (uint32_t)__cvta_generic_to_shared(sm);

    // stage B via cp.async (no conversion needed)
    {
        const float* Bg = eWt + (d << 14);
#pragma unroll
        for (int j = 0; j < 16; ++j) {
            int c = tid + j * 256;                 // 4096 float4 chunks
            int n = c >> 5, f4 = (c & 31) << 2;
            uint32_t dst = smb + ((256 * ZSA + n * ZSA + f4) << 2);
            asm volatile("cp.async.cg.shared.global [%0], [%1], 16;"
                         :: "r"(dst), "l"(Bg + n * H_ + f4));
        }
        asm volatile("cp.async.commit_group;");
    }
    // stage A with tf32 rounding (coalesced)
#pragma unroll
    for (int j = 0; j < 32; ++j) {
        int c = tid + j * 256;                     // 8192 float4 chunks
        int r = c >> 5, f4 = (c & 31) << 2;
        float4 v = *reinterpret_cast<const float4*>(g_h + (m0 + r) * H_ + f4);
        v.x = tf32r(v.x); v.y = tf32r(v.y); v.z = tf32r(v.z); v.w = tf32r(v.w);
        *reinterpret_cast<float4*>(A_s + r * ZSA + f4) = v;
    }
    asm volatile("cp.async.wait_group 0;");
    __syncthreads();

    // per-lane ldmatrix base addresses
    const int mrow = (lane & 7) + ((lane >> 3) & 1) * 8;
    const int coff = (lane >> 4) * 4;
    uint32_t aad[4], bad[4];
#pragma unroll
    for (int mt = 0; mt < 4; ++mt)
        aad[mt] = smb + (((wm * 64 + mt * 16 + mrow) * ZSA + coff) << 2);
#pragma unroll
    for (int nt = 0; nt < 4; ++nt)
        bad[nt] = smb + ((256 * ZSA + (wn * 64 + nt * 16 + mrow) * ZSA + coff) << 2);

    float acc[4][8][4];
#pragma unroll
    for (int mt = 0; mt < 4; ++mt)
#pragma unroll
        for (int j = 0; j < 8; ++j)
#pragma unroll
            for (int p = 0; p < 4; ++p) acc[mt][j][p] = 0.f;

#pragma unroll 4
    for (int ks = 0; ks < 16; ++ks) {
        const uint32_t ko = ks * 32;               // 8 floats
        uint32_t Af[4][4];
#pragma unroll
        for (int mt = 0; mt < 4; ++mt)
            LDSM4(Af[mt][0], Af[mt][1], Af[mt][2], Af[mt][3], aad[mt] + ko);
#pragma unroll
        for (int nt = 0; nt < 4; ++nt) {
            uint32_t Bf[4];
            LDSM4(Bf[0], Bf[1], Bf[2], Bf[3], bad[nt] + ko);
#pragma unroll
            for (int mt = 0; mt < 4; ++mt) {
                MMA_TF32(acc[mt][2 * nt],     Af[mt], Bf[0], Bf[2]);
                MMA_TF32(acc[mt][2 * nt + 1], Af[mt], Bf[1], Bf[3]);
            }
        }
    }

    // epilogue: write z tile
#pragma unroll
    for (int mt = 0; mt < 4; ++mt) {
        int r = m0 + wm * 64 + mt * 16 + (lane >> 2);
        float* zr0 = g_z + (size_t)r * ZW_ + d * H_;
        float* zr1 = zr0 + 8 * ZW_;
#pragma unroll
        for (int j = 0; j < 8; ++j) {
            int col = wn * 64 + (j >> 1) * 16 + (j & 1) * 8 + (lane & 3) * 2;
            float2 lo = make_float2(acc[mt][j][0], acc[mt][j][1]);
            float2 hi = make_float2(acc[mt][j][2], acc[mt][j][3]);
            *reinterpret_cast<float2*>(zr0 + col) = lo;
            *reinterpret_cast<float2*>(zr1 + col) = hi;
        }
    }
}

// ---------------- combine: msg[e] = sum_d ea[e,d]*z[src[e],d,:] -> agg[dst] ----------------
// warp per edge: 32 lanes x 4 outputs (float4), 8 edges per 256-thread block.
__global__ void __launch_bounds__(256)
combine_kernel(const int* __restrict__ edge_index,
               const float* __restrict__ edge_attr,
               float* __restrict__ aggp) {
    int e    = blockIdx.x * 8 + (threadIdx.x >> 5);
    int lane = threadIdx.x & 31;
    int src = edge_index[e];
    int dst = edge_index[E_ + e];
    const float* zr  = g_z + (size_t)src * ZW_ + lane * 4;
    const float* ear = edge_attr + e * ED_;
    float4 acc = *reinterpret_cast<const float4*>(zr + 16 * H_);   // bias chunk
#pragma unroll
    for (int d = 0; d < 16; ++d) {
        float a = ear[d];
        float4 v = *reinterpret_cast<const float4*>(zr + d * H_);
        acc.x += a * v.x; acc.y += a * v.y;
        acc.z += a * v.z; acc.w += a * v.w;
    }
    float* ap = aggp + dst * H_ + lane * 4;
    atomicAdd(ap,     acc.x);
    atomicAdd(ap + 1, acc.y);
    atomicAdd(ap + 2, acc.z);
    atomicAdd(ap + 3, acc.w);
}

// ---------------- x_new = h @ root_W + agg/deg + bias ; BN stats ----------------
// 256 threads: two 128-thread halves, 8 nodes each; stats block-reduced.
__global__ void __launch_bounds__(256)
xnew_kernel(const float* __restrict__ rootW, const float* __restrict__ cbias,
            const float* __restrict__ aggp, float* __restrict__ statp) {
    __shared__ float ps[128], pq[128];
    int o    = threadIdx.x & 127;
    int half = threadIdx.x >> 7;
    int r0   = blockIdx.x * 16 + half * 8;
    float acc[8];
#pragma unroll
    for (int r = 0; r < 8; ++r) acc[r] = 0.f;
    for (int k = 0; k < H_; ++k) {
        float w = rootW[k * H_ + o];
#pragma unroll
        for (int r = 0; r < 8; ++r) acc[r] += g_h[(r0 + r) * H_ + k] * w;
    }
    float cb = cbias[o];
    float s = 0.f, sq = 0.f;
#pragma unroll
    for (int r = 0; r < 8; ++r) {
        int n = r0 + r;
        float v = acc[r] + aggp[n * H_ + o] / fmaxf(g_deg[n], 1.f) + cb;
        g_xnew[n * H_ + o] = v;
        s += v;
        sq += v * v;
    }
    if (half) { ps[o] = s; pq[o] = sq; }
    __syncthreads();
    if (!half) {
        atomicAdd(&statp[o],      s  + ps[o]);
        atomicAdd(&statp[H_ + o], sq + pq[o]);
    }
}

// ---------------- BN + ReLU + residual (+ pool on last layer) ----------------
__global__ void bn_kernel(const float* __restrict__ gamma,
                          const float* __restrict__ beta,
                          const float* __restrict__ statp,
                          const int* __restrict__ batch, int last) {
    int idx = blockIdx.x * 256 + threadIdx.x;   // N*H threads
    int o = idx & (H_ - 1);
    float mu  = statp[o] * (1.f / N_);
    float var = statp[H_ + o] * (1.f / N_) - mu * mu;
    float v = (g_xnew[idx] - mu) * rsqrtf(var + BN_EPS) * gamma[o] + beta[o];
    float hv = g_h[idx] + fmaxf(v, 0.f);
    g_h[idx] = hv;
    if (last) {
        int n = idx >> 7;
        atomicAdd(&g_pool[batch[n] * H_ + o], hv);
    }
}

// ---------------- classifier ----------------
__global__ void __launch_bounds__(64)
cls_kernel(const float* __restrict__ W1, const float* __restrict__ b1,
           const float* __restrict__ W2, const float* __restrict__ b2,
           float* __restrict__ out) {
    __shared__ float gv[H_];
    __shared__ float part[2];
    int g = blockIdx.x, j = threadIdx.x;        // 64 threads
    float inv = 1.f / fmaxf(g_gcnt[g], 1.f);
    gv[j]      = g_pool[g * H_ + j] * inv;
    gv[j + 64] = g_pool[g * H_ + 64 + j] * inv;
    __syncthreads();
    float a = b1[j];
    for (int k = 0; k < H_; ++k) a += gv[k] * W1[k * 64 + j];
    float v = fmaxf(a, 0.f) * W2[j];
#pragma unroll
    for (int off = 16; off > 0; off >>= 1)
        v += __shfl_down_sync(0xffffffffu, v, off);
    if ((j & 31) == 0) part[j >> 5] = v;
    __syncthreads();
    if (j == 0) out[g] = part[0] + part[1] + b2[0];
}

// ---------------- launch ----------------
extern "C" void kernel_launch(void* const* d_in, const int* in_sizes, int n_in,
                              void* d_out, int out_size) {
    const float* x          = (const float*)d_in[0];
    const int*   edge_index = (const int*)  d_in[1];
    const float* edge_attr  = (const float*)d_in[2];
    const int*   batch      = (const int*)  d_in[3];
    const float* node_W     = (const float*)d_in[4];
    const float* node_b     = (const float*)d_in[5];
    const float* edge_W     = (const float*)d_in[6];
    const float* edge_b     = (const float*)d_in[7];
    const float* root_W     = (const float*)d_in[8];
    const float* conv_bias  = (const float*)d_in[9];
    const float* bn_gamma   = (const float*)d_in[10];
    const float* bn_beta    = (const float*)d_in[11];
    const float* cls_W1     = (const float*)d_in[12];
    const float* cls_b1     = (const float*)d_in[13];
    const float* cls_W2     = (const float*)d_in[14];
    const float* cls_b2     = (const float*)d_in[15];
    float* out = (float*)d_out;

    float* d_agg3;  cudaGetSymbolAddress((void**)&d_agg3,  g_agg3);
    float* d_stats; cudaGetSymbolAddress((void**)&d_stats, g_stats);
    float* d_eWt;   cudaGetSymbolAddress((void**)&d_eWt,   g_eWt);

    const int zsmem = ZSMEM_F * 4;   // ~198 KB
    cudaFuncSetAttribute((const void*)zgemm_kernel,
                         cudaFuncAttributeMaxDynamicSharedMemorySize, zsmem);

    init_kernel<<<(L_ * KD_ * H_ * H_ + 255) / 256, 256>>>(edge_W, edge_b);
    counts_kernel<<<(E_ + 255) / 256, 256>>>(edge_index, batch);
    enc_kernel<<<(N_ * H_) / 256, 256>>>(x, node_W, node_b);

    for (int l = 0; l < L_; ++l) {
        zgemm_kernel<<<dim3(N_ / 256, KD_), 256, zsmem>>>(
            d_eWt + (size_t)l * KD_ * H_ * H_);
        combine_kernel<<<E_ / 8, 256>>>(edge_index, edge_attr,
                                        d_agg3 + (size_t)l * N_ * H_);
        xnew_kernel<<<N_ / 16, 256>>>(root_W + l * H_ * H_, conv_bias + l * H_,
                                      d_agg3 + (size_t)l * N_ * H_,
                                      d_stats + l * 2 * H_);
        bn_kernel<<<(N_ * H_) / 256, 256>>>(bn_gamma + l * H_, bn_beta + l * H_,
                                            d_stats + l * 2 * H_, batch,
                                            l == L_ - 1);
    }

    cls_kernel<<<G_, 64>>>(cls_W1, cls_b1, cls_W2, cls_b2, out);
}

// round 4
// speedup vs baseline: 8.2249x; 1.5084x over previous
#include <cuda_runtime.h>
#include <cstdint>

#define N_  2048
#define E_  8192
#define ND_ 32
#define ED_ 16
#define H_  128
#define G_  128
#define L_  3
#define KD_ 18          // 16 edge dims + edge bias + root_W
#define ZW_ (KD_ * H_)  // 2304, z row width
#define BN_EPS 1e-5f

// ---------------- device scratch (no allocations allowed) ----------------
__device__ float g_h[N_ * H_];
__device__ float g_xnew[N_ * H_];
__device__ float g_agg3[L_ * N_ * H_];
__device__ float g_deg[N_];
__device__ float g_stats[L_ * 2 * H_];
__device__ float g_pool[G_ * H_];
__device__ float g_gcnt[G_];
__device__ float g_z[N_ * ZW_];                 // per-node transforms, 18.9 MB
__device__ float g_eWt[L_ * KD_ * H_ * H_];     // tf32, [l][d][n=o][k=i]
__device__ int   g_scnt[N_];                    // src counts
__device__ int   g_scur[N_];
__device__ int   g_soff[N_];                    // exclusive offsets
__device__ int   g_perm[E_];                    // edges sorted by src

// ---------------- helpers ----------------
__device__ __forceinline__ float tf32r(float x) {
    uint32_t u;
    asm("cvt.rna.tf32.f32 %0, %1;" : "=r"(u) : "f"(x));
    return __uint_as_float(u);
}

#define LDSM4(r0, r1, r2, r3, addr)                                          \
    asm volatile("ldmatrix.sync.aligned.m8n8.x4.shared.b16 {%0,%1,%2,%3}, [%4];" \
                 : "=r"(r0), "=r"(r1), "=r"(r2), "=r"(r3) : "r"(addr))

#define MMA_TF32(c, a, b0, b1)                                               \
    asm volatile("mma.sync.aligned.m16n8k8.row.col.f32.tf32.tf32.f32 "       \
                 "{%0,%1,%2,%3}, {%4,%5,%6,%7}, {%8,%9}, {%0,%1,%2,%3};"     \
                 : "+f"((c)[0]), "+f"((c)[1]), "+f"((c)[2]), "+f"((c)[3])    \
                 : "r"((a)[0]), "r"((a)[1]), "r"((a)[2]), "r"((a)[3]),       \
                   "r"(b0), "r"(b1))

// ---------------- init: zero scratch + prep tf32-transposed weights ----------------
__global__ void init_kernel(const float* __restrict__ edge_W,
                            const float* __restrict__ edge_b,
                            const float* __restrict__ root_W) {
    int i = blockIdx.x * 256 + threadIdx.x;     // grid covers L*18*16384
    if (i < L_ * N_ * H_)  g_agg3[i] = 0.f;
    if (i < N_)          { g_deg[i] = 0.f; g_scnt[i] = 0; g_scur[i] = 0; }
    if (i < G_)            g_gcnt[i] = 0.f;
    if (i < G_ * H_)       g_pool[i] = 0.f;
    if (i < L_ * 2 * H_)   g_stats[i] = 0.f;
    if (i < L_ * KD_ * H_ * H_) {
        int ld = i >> 14, j = i & 16383;
        int l = ld / KD_, d = ld - l * KD_;
        int n = j >> 7, k = j & 127;
        float v;
        if (d < 16)       v = edge_W[((l * 16 + d) << 14) + k * H_ + n];
        else if (d == 16) v = edge_b[(l << 14) + k * H_ + n];
        else              v = root_W[(l * H_ + k) * H_ + n];
        g_eWt[i] = tf32r(v);
    }
}

// ---------------- degree / src counts / graph-size counts ----------------
__global__ void counts_kernel(const int* __restrict__ edge_index,
                              const int* __restrict__ batch) {
    int i = blockIdx.x * 256 + threadIdx.x;
    if (i < E_) {
        atomicAdd(&g_deg[edge_index[E_ + i]], 1.f);
        atomicAdd(&g_scnt[edge_index[i]], 1);
    }
    if (i < N_) atomicAdd(&g_gcnt[batch[i]], 1.f);
}

// ---------------- exclusive scan of src counts (single block, 1024 thr) ----------------
__global__ void __launch_bounds__(1024)
scan_kernel() {
    __shared__ int a[2048], b[2048];
    int t = threadIdx.x;
    a[t] = g_scnt[t]; a[t + 1024] = g_scnt[t + 1024];
    __syncthreads();
    int* s = a; int* d2 = b;
#pragma unroll
    for (int off = 1; off < 2048; off <<= 1) {
        d2[t]        = s[t]        + (t        >= off ? s[t - off]        : 0);
        d2[t + 1024] = s[t + 1024] + (t + 1024 >= off ? s[t + 1024 - off] : 0);
        __syncthreads();
        int* tmp = s; s = d2; d2 = tmp;
    }
    g_soff[t]        = t ? s[t - 1] : 0;
    g_soff[t + 1024] = s[t + 1023];
}

// ---------------- scatter: perm = edge ids sorted by src ----------------
__global__ void scatter_kernel(const int* __restrict__ edge_index) {
    int i = blockIdx.x * 256 + threadIdx.x;
    if (i < E_) {
        int src = edge_index[i];
        int pos = g_soff[src] + atomicAdd(&g_scur[src], 1);
        g_perm[pos] = i;
    }
}

// ---------------- node encoder: elementwise thread per (n,o) ----------------
__global__ void __launch_bounds__(256)
enc_kernel(const float* __restrict__ x, const float* __restrict__ nW,
           const float* __restrict__ nb) {
    int idx = blockIdx.x * 256 + threadIdx.x;   // N*H
    int n = idx >> 7, o = idx & 127;
    const float* xr = x + n * ND_;
    float acc = nb[o];
#pragma unroll
    for (int k = 0; k < ND_; ++k) acc += xr[k] * nW[k * H_ + o];
    g_h[idx] = acc;
}

// ---------------- zgemm: z = tf32(h) @ eWt  (M=2048, N=KD*128, K=128) ----------------
// grid (8, 18) = 144 CTAs = one wave. 256 thr, warp tile 64x64,
// fragment double-buffered k loop (LDSM for k+1 overlaps MMA for k).
#define ZSA 132
#define ZSMEM_F (256 * ZSA + 128 * ZSA)

__global__ void __launch_bounds__(256, 1)
zgemm_kernel(const float* __restrict__ eWt) {      // g_eWt + l*KD*16384
    extern __shared__ float sm[];
    float* A_s = sm;                 // [256][132] tf32(h)
    float* B_s = sm + 256 * ZSA;     // [128][132] weights (n-major, k contig)

    const int tid  = threadIdx.x;
    const int lane = tid & 31;
    const int wid  = tid >> 5;
    const int wm   = wid >> 1;
    const int wn   = wid & 1;
    const int m0   = blockIdx.x * 256;
    const int d    = blockIdx.y;

    const uint32_t smb = (uint32_t)__cvta_generic_to_shared(sm);

    {
        const float* Bg = eWt + (d << 14);
#pragma unroll
        for (int j = 0; j < 16; ++j) {
            int c = tid + j * 256;
            int n = c >> 5, f4 = (c & 31) << 2;
            uint32_t dst = smb + ((256 * ZSA + n * ZSA + f4) << 2);
            asm volatile("cp.async.cg.shared.global [%0], [%1], 16;"
                         :: "r"(dst), "l"(Bg + n * H_ + f4));
        }
        asm volatile("cp.async.commit_group;");
    }
#pragma unroll
    for (int j = 0; j < 32; ++j) {
        int c = tid + j * 256;
        int r = c >> 5, f4 = (c & 31) << 2;
        float4 v = *reinterpret_cast<const float4*>(g_h + (m0 + r) * H_ + f4);
        v.x = tf32r(v.x); v.y = tf32r(v.y); v.z = tf32r(v.z); v.w = tf32r(v.w);
        *reinterpret_cast<float4*>(A_s + r * ZSA + f4) = v;
    }
    asm volatile("cp.async.wait_group 0;");
    __syncthreads();

    const int mrow = (lane & 7) + ((lane >> 3) & 1) * 8;
    const int coff = (lane >> 4) * 4;
    uint32_t aad[4], bad[4];
#pragma unroll
    for (int mt = 0; mt < 4; ++mt)
        aad[mt] = smb + (((wm * 64 + mt * 16 + mrow) * ZSA + coff) << 2);
#pragma unroll
    for (int nt = 0; nt < 4; ++nt)
        bad[nt] = smb + ((256 * ZSA + (wn * 64 + nt * 16 + mrow) * ZSA + coff) << 2);

    float acc[4][8][4];
#pragma unroll
    for (int mt = 0; mt < 4; ++mt)
#pragma unroll
        for (int j = 0; j < 8; ++j)
#pragma unroll
            for (int p = 0; p < 4; ++p) acc[mt][j][p] = 0.f;

    uint32_t Af[2][4][4], Bf[2][4][4];

#define LOAD_STAGE(buf, ko)                                                   \
    do {                                                                      \
        _Pragma("unroll")                                                     \
        for (int mt = 0; mt < 4; ++mt)                                        \
            LDSM4(Af[buf][mt][0], Af[buf][mt][1], Af[buf][mt][2],             \
                  Af[buf][mt][3], aad[mt] + (ko));                            \
        _Pragma("unroll")                                                     \
        for (int nt = 0; nt < 4; ++nt)                                        \
            LDSM4(Bf[buf][nt][0], Bf[buf][nt][1], Bf[buf][nt][2],             \
                  Bf[buf][nt][3], bad[nt] + (ko));                            \
    } while (0)

    LOAD_STAGE(0, 0u);
#pragma unroll
    for (int ks = 0; ks < 16; ++ks) {
        const int cur = ks & 1;
        if (ks < 15) {
            const uint32_t ko = (uint32_t)(ks + 1) * 32;
            if (cur == 0) LOAD_STAGE(1, ko); else LOAD_STAGE(0, ko);
        }
#pragma unroll
        for (int nt = 0; nt < 4; ++nt)
#pragma unroll
            for (int mt = 0; mt < 4; ++mt) {
                MMA_TF32(acc[mt][2 * nt],     Af[cur][mt], Bf[cur][nt][0], Bf[cur][nt][2]);
                MMA_TF32(acc[mt][2 * nt + 1], Af[cur][mt], Bf[cur][nt][1], Bf[cur][nt][3]);
            }
    }
#undef LOAD_STAGE

    // epilogue: write z tile
#pragma unroll
    for (int mt = 0; mt < 4; ++mt) {
        int r = m0 + wm * 64 + mt * 16 + (lane >> 2);
        float* zr0 = g_z + (size_t)r * ZW_ + d * H_;
        float* zr1 = zr0 + 8 * ZW_;
#pragma unroll
        for (int j = 0; j < 8; ++j) {
            int col = wn * 64 + (j >> 1) * 16 + (j & 1) * 8 + (lane & 3) * 2;
            *reinterpret_cast<float2*>(zr0 + col) = make_float2(acc[mt][j][0], acc[mt][j][1]);
            *reinterpret_cast<float2*>(zr1 + col) = make_float2(acc[mt][j][2], acc[mt][j][3]);
        }
    }
}

// ---------------- combine: msg[e] = sum_d ea[e,d]*z[src[e],d,:] -> agg[dst] ----------------
// warp per edge, edges visited in src-sorted order (L1 reuse of z rows).
__global__ void __launch_bounds__(256)
combine_kernel(const int* __restrict__ edge_index,
               const float* __restrict__ edge_attr,
               float* __restrict__ aggp) {
    int j    = blockIdx.x * 8 + (threadIdx.x >> 5);
    int lane = threadIdx.x & 31;
    int e   = g_perm[j];
    int src = edge_index[e];
    int dst = edge_index[E_ + e];
    const float* zr = g_z + (size_t)src * ZW_ + lane * 4;
    float ea[16];
    {
        const float4* eap = reinterpret_cast<const float4*>(edge_attr + e * ED_);
#pragma unroll
        for (int q = 0; q < 4; ++q) {
            float4 v = eap[q];
            ea[4 * q] = v.x; ea[4 * q + 1] = v.y; ea[4 * q + 2] = v.z; ea[4 * q + 3] = v.w;
        }
    }
    float4 acc = *reinterpret_cast<const float4*>(zr + 16 * H_);   // bias chunk
#pragma unroll
    for (int d = 0; d < 16; ++d) {
        float a = ea[d];
        float4 v = *reinterpret_cast<const float4*>(zr + d * H_);
        acc.x += a * v.x; acc.y += a * v.y;
        acc.z += a * v.z; acc.w += a * v.w;
    }
    float* ap = aggp + dst * H_ + lane * 4;
    atomicAdd(ap,     acc.x);
    atomicAdd(ap + 1, acc.y);
    atomicAdd(ap + 2, acc.z);
    atomicAdd(ap + 3, acc.w);
}

// ---------------- x_new = z[:,17] + agg/deg + bias ; BN stats (elementwise) ----------------
__global__ void __launch_bounds__(256)
xnew_kernel(const float* __restrict__ cbias,
            const float* __restrict__ aggp, float* __restrict__ statp) {
    __shared__ float ps[128], pq[128];
    int o    = threadIdx.x & 127;
    int half = threadIdx.x >> 7;
    int r0   = blockIdx.x * 16 + half * 8;
    float cb = cbias[o];
    float s = 0.f, sq = 0.f;
#pragma unroll
    for (int r = 0; r < 8; ++r) {
        int n = r0 + r;
        float v = g_z[(size_t)n * ZW_ + 17 * H_ + o]
                + aggp[n * H_ + o] / fmaxf(g_deg[n], 1.f) + cb;
        g_xnew[n * H_ + o] = v;
        s += v;
        sq += v * v;
    }
    if (half) { ps[o] = s; pq[o] = sq; }
    __syncthreads();
    if (!half) {
        atomicAdd(&statp[o],      s  + ps[o]);
        atomicAdd(&statp[H_ + o], sq + pq[o]);
    }
}

// ---------------- BN + ReLU + residual (+ pool on last layer) ----------------
__global__ void bn_kernel(const float* __restrict__ gamma,
                          const float* __restrict__ beta,
                          const float* __restrict__ statp,
                          const int* __restrict__ batch, int last) {
    int idx = blockIdx.x * 256 + threadIdx.x;   // N*H threads
    int o = idx & (H_ - 1);
    float mu  = statp[o] * (1.f / N_);
    float var = statp[H_ + o] * (1.f / N_) - mu * mu;
    float v = (g_xnew[idx] - mu) * rsqrtf(var + BN_EPS) * gamma[o] + beta[o];
    float hv = g_h[idx] + fmaxf(v, 0.f);
    g_h[idx] = hv;
    if (last) {
        int n = idx >> 7;
        atomicAdd(&g_pool[batch[n] * H_ + o], hv);
    }
}

// ---------------- classifier ----------------
__global__ void __launch_bounds__(64)
cls_kernel(const float* __restrict__ W1, const float* __restrict__ b1,
           const float* __restrict__ W2, const float* __restrict__ b2,
           float* __restrict__ out) {
    __shared__ float gv[H_];
    __shared__ float part[2];
    int g = blockIdx.x, j = threadIdx.x;        // 64 threads
    float inv = 1.f / fmaxf(g_gcnt[g], 1.f);
    gv[j]      = g_pool[g * H_ + j] * inv;
    gv[j + 64] = g_pool[g * H_ + 64 + j] * inv;
    __syncthreads();
    float a = b1[j];
    for (int k = 0; k < H_; ++k) a += gv[k] * W1[k * 64 + j];
    float v = fmaxf(a, 0.f) * W2[j];
#pragma unroll
    for (int off = 16; off > 0; off >>= 1)
        v += __shfl_down_sync(0xffffffffu, v, off);
    if ((j & 31) == 0) part[j >> 5] = v;
    __syncthreads();
    if (j == 0) out[g] = part[0] + part[1] + b2[0];
}

// ---------------- launch ----------------
extern "C" void kernel_launch(void* const* d_in, const int* in_sizes, int n_in,
                              void* d_out, int out_size) {
    const float* x          = (const float*)d_in[0];
    const int*   edge_index = (const int*)  d_in[1];
    const float* edge_attr  = (const float*)d_in[2];
    const int*   batch      = (const int*)  d_in[3];
    const float* node_W     = (const float*)d_in[4];
    const float* node_b     = (const float*)d_in[5];
    const float* edge_W     = (const float*)d_in[6];
    const float* edge_b     = (const float*)d_in[7];
    const float* root_W     = (const float*)d_in[8];
    const float* conv_bias  = (const float*)d_in[9];
    const float* bn_gamma   = (const float*)d_in[10];
    const float* bn_beta    = (const float*)d_in[11];
    const float* cls_W1     = (const float*)d_in[12];
    const float* cls_b1     = (const float*)d_in[13];
    const float* cls_W2     = (const float*)d_in[14];
    const float* cls_b2     = (const float*)d_in[15];
    float* out = (float*)d_out;

    float* d_agg3;  cudaGetSymbolAddress((void**)&d_agg3,  g_agg3);
    float* d_stats; cudaGetSymbolAddress((void**)&d_stats, g_stats);
    float* d_eWt;   cudaGetSymbolAddress((void**)&d_eWt,   g_eWt);

    const int zsmem = ZSMEM_F * 4;   // ~198 KB
    cudaFuncSetAttribute((const void*)zgemm_kernel,
                         cudaFuncAttributeMaxDynamicSharedMemorySize, zsmem);

    init_kernel<<<(L_ * KD_ * H_ * H_ + 255) / 256, 256>>>(edge_W, edge_b, root_W);
    counts_kernel<<<(E_ + 255) / 256, 256>>>(edge_index, batch);
    scan_kernel<<<1, 1024>>>();
    scatter_kernel<<<(E_ + 255) / 256, 256>>>(edge_index);
    enc_kernel<<<(N_ * H_) / 256, 256>>>(x, node_W, node_b);

    for (int l = 0; l < L_; ++l) {
        zgemm_kernel<<<dim3(N_ / 256, KD_), 256, zsmem>>>(
            d_eWt + (size_t)l * KD_ * H_ * H_);
        combine_kernel<<<E_ / 8, 256>>>(edge_index, edge_attr,
                                        d_agg3 + (size_t)l * N_ * H_);
        xnew_kernel<<<N_ / 16, 256>>>(conv_bias + l * H_,
                                      d_agg3 + (size_t)l * N_ * H_,
                                      d_stats + l * 2 * H_);
        bn_kernel<<<(N_ * H_) / 256, 256>>>(bn_gamma + l * H_, bn_beta + l * H_,
                                            d_stats + l * 2 * H_, batch,
                                            l == L_ - 1);
    }

    cls_kernel<<<G_, 64>>>(cls_W1, cls_b1, cls_W2, cls_b2, out);
}